// round 11
// baseline (speedup 1.0000x reference)
#include <cuda_runtime.h>
#include <cuda_fp16.h>
#include <cstdint>
#include <math.h>

#define BDIM 64
#define SDIM 2048
#define HDIM 1024
#define KDIM 2048   // 2H (contraction)
#define NDIM 1024   // H  (energy dim)

#define BM 128
#define BN 128
#define BK 32        // k elems per tile
#define PADH 40      // fp16 row pitch in halves (80B, conflict-free LDSM)

#define A32_STG 16384                 // 128 rows x 128B (fp32, SW128)
#define A16_STG (BM * PADH * 2)       // 10240
#define B_STG   (BN * PADH * 2)       // 10240
#define A32_OFF 0
#define A16_OFF (3 * A32_STG)                 // 49152
#define B_OFF   (A16_OFF + 2 * A16_STG)       // 69632
#define EPI_OFF (B_OFF + 4 * B_STG)           // 110592
#define SMEM_TOTAL (EPI_OFF + 2048)           // 112640

// ---- device scratch (allocation-free rule: __device__ globals) ----
__device__ float  g_hWh[BDIM * NDIM];               // hidden@Wh + b_attn
__device__ float  g_part[8 * BDIM * SDIM];          // per-nTile partial scores
__device__ __half g_WhT[(size_t)NDIM * KDIM];       // We^T in fp16 [N][K] (4MB)

// ---------------------------------------------------------------- helpers
__device__ __forceinline__ void cpa16(uint32_t s, const void* g) {
  asm volatile("cp.async.cg.shared.global [%0], [%1], 16;\n" :: "r"(s), "l"(g));
}
__device__ __forceinline__ uint32_t smem_u32(const void* p) {
  uint32_t a;
  asm("{ .reg .u64 t; cvta.to.shared.u64 t, %1; cvt.u32.u64 %0, t; }" : "=r"(a) : "l"(p));
  return a;
}
__device__ __forceinline__ void mma16(float* d, const uint32_t* a, const uint32_t* b) {
  asm volatile(
    "mma.sync.aligned.m16n8k16.row.col.f32.f16.f16.f32 "
    "{%0,%1,%2,%3}, {%4,%5,%6,%7}, {%8,%9}, {%0,%1,%2,%3};\n"
    : "+f"(d[0]), "+f"(d[1]), "+f"(d[2]), "+f"(d[3])
    : "r"(a[0]), "r"(a[1]), "r"(a[2]), "r"(a[3]), "r"(b[0]), "r"(b[1]));
}
__device__ __forceinline__ void ldsm4(uint32_t& r0, uint32_t& r1,
                                      uint32_t& r2, uint32_t& r3, uint32_t addr) {
  asm volatile("ldmatrix.sync.aligned.m8n8.x4.shared.b16 {%0,%1,%2,%3}, [%4];"
               : "=r"(r0), "=r"(r1), "=r"(r2), "=r"(r3) : "r"(addr));
}

// ----------------------- kernel 0: WhT[n][k] = fp16(W[H+k][n]) transpose
__global__ void wt_kernel(const float* __restrict__ W) {
  __shared__ float t[32][33];
  const int n0 = blockIdx.x * 32;
  const int k0 = blockIdx.y * 32;
  const int tx = threadIdx.x, ty = threadIdx.y;   // 32 x 8
  #pragma unroll
  for (int i = 0; i < 4; i++)
    t[ty + i * 8][tx] = W[(size_t)(HDIM + k0 + ty + i * 8) * NDIM + n0 + tx];
  __syncthreads();
  #pragma unroll
  for (int i = 0; i < 4; i++)
    g_WhT[(size_t)(n0 + ty + i * 8) * KDIM + k0 + tx] =
        __float2half_rn(t[tx][ty + i * 8]);
}

// ------------------------------------------------- kernel 1: hWh + b_attn
__global__ void hwh_kernel(const float* __restrict__ hidden,
                           const float* __restrict__ W,
                           const float* __restrict__ b_attn) {
  const int n = blockIdx.x * 256 + threadIdx.x;
  const int b = blockIdx.y;
  const float* hrow = hidden + (long long)b * HDIM;
  float a0 = 0.f, a1 = 0.f, a2 = 0.f, a3 = 0.f;   // break FMA dep chain
  for (int h = 0; h < HDIM; h += 4) {
    a0 = fmaf(hrow[h    ], W[(long long)(h    ) * NDIM + n], a0);
    a1 = fmaf(hrow[h + 1], W[(long long)(h + 1) * NDIM + n], a1);
    a2 = fmaf(hrow[h + 2], W[(long long)(h + 2) * NDIM + n], a2);
    a3 = fmaf(hrow[h + 3], W[(long long)(h + 3) * NDIM + n], a3);
  }
  g_hWh[(long long)b * NDIM + n] = (a0 + a1) + (a2 + a3) + b_attn[n];
}

// ------------------------------------ per-ktile loader: A fp32 + B fp16
__device__ __forceinline__ void load_group(uint32_t smb, const float* Ag,
                                           const __half* Bg, int kt, int tid) {
  // A: 128 rows x 8 x 16B (fp32, SW128 swizzle), 4 chunks/thread
  const uint32_t a32 = smb + A32_OFF + (uint32_t)(kt % 3) * A32_STG;
  #pragma unroll
  for (int i = 0; i < 4; i++) {
    const int c = tid * 4 + i;
    const int r = c >> 3, u = c & 7;
    cpa16(a32 + (uint32_t)(r * 128 + ((u ^ (r & 7)) * 16)),
          Ag + (size_t)r * KDIM + kt * BK + u * 4);
  }
  // B: 128 rows x 4 x 16B (fp16, padded linear), 2 chunks/thread
  const uint32_t bb = smb + B_OFF + (uint32_t)(kt & 3) * B_STG;
  #pragma unroll
  for (int i = 0; i < 2; i++) {
    const int c = tid * 2 + i;
    const int r = c >> 2, q = c & 3;
    cpa16(bb + (uint32_t)((r * PADH + q * 8) * 2),
          Bg + (size_t)r * KDIM + kt * BK + q * 8);
  }
  asm volatile("cp.async.commit_group;\n" ::: "memory");
}

// -------------------- convert tile kt: fp32 stage -> fp16 buffer (kt&1)
__device__ __forceinline__ void cvt_tile(char* dynsm, uint32_t smb, int kt, int tid) {
  const int r = tid >> 1;             // 0..127
  const int hseg = tid & 1;           // halves 0..15 / 16..31
  const char* src = dynsm + A32_OFF + (size_t)(kt % 3) * A32_STG + r * 128;
  char* dst = dynsm + A16_OFF + (size_t)(kt & 1) * A16_STG + (r * PADH + hseg * 16) * 2;
  uint4 o[2];
  #pragma unroll
  for (int j = 0; j < 4; j++) {
    const float4 f = *(const float4*)(src + (((hseg * 4 + j) ^ (r & 7)) * 16));
    __half2 lo = __floats2half2_rn(f.x, f.y);
    __half2 hi = __floats2half2_rn(f.z, f.w);
    ((__half2*)o)[j * 2]     = lo;
    ((__half2*)o)[j * 2 + 1] = hi;
  }
  *(uint4*)dst = o[0];
  *(uint4*)(dst + 16) = o[1];
}

// ------------- kernel 2: fused E = enc@We (fp16 MMA) ; p = v·tanh(E+hWh)
__global__ __launch_bounds__(256, 2)
void energy_fp16_kernel(const float* __restrict__ enc,
                        const float* __restrict__ v) {
  extern __shared__ __align__(16) char dynsm[];
  float* s_hwh = (float*)(dynsm + EPI_OFF);
  float* s_v   = s_hwh + BN;
  float* s_red = s_v + BN;                 // [2][BM]
  const uint32_t smb = smem_u32(dynsm);

  const int tid  = threadIdx.x;
  const int lane = tid & 31;
  const int wid  = tid >> 5;
  const int wm   = wid & 3;    // warp grid 4(M) x 2(N)
  const int wn   = wid >> 2;
  const int grp  = lane >> 2;
  const int qp   = lane & 3;

  const int mt  = blockIdx.y;            // 0..1023
  const int n0  = blockIdx.x * BN;       // x fastest => L2 reuse of A
  const size_t row0 = (size_t)mt * BM;
  const int bidx = mt >> 4;

  const float*  Ag = enc + row0 * KDIM;            // fp32 directly!
  const __half* Bg = g_WhT + (size_t)n0 * KDIM;

  // ---- ldmatrix per-lane byte offsets ----
  const int l8 = lane & 7;
  const int lm = lane >> 3;
  uint32_t aOff[2];
  #pragma unroll
  for (int mf = 0; mf < 2; mf++) {
    const int row = wm * 32 + mf * 16 + l8 + (lm & 1) * 8;
    const int col = (lm >> 1) * 8;
    aOff[mf] = smb + A16_OFF + (uint32_t)((row * PADH + col) * 2);
  }
  uint32_t bOff[4];
  #pragma unroll
  for (int nfp = 0; nfp < 4; nfp++) {
    const int row = wn * 64 + nfp * 16 + l8 + (lm >> 1) * 8;
    const int col = (lm & 1) * 8;
    bOff[nfp] = smb + B_OFF + (uint32_t)((row * PADH + col) * 2);
  }

  float acc[2][8][4];
  #pragma unroll
  for (int i = 0; i < 2; i++)
    #pragma unroll
    for (int j = 0; j < 8; j++)
      #pragma unroll
      for (int e = 0; e < 4; e++) acc[i][j][e] = 0.f;

  const int KT = KDIM / BK;  // 64
  load_group(smb, Ag, Bg, 0, tid);
  load_group(smb, Ag, Bg, 1, tid);
  load_group(smb, Ag, Bg, 2, tid);
  if (tid < BN) {
    s_hwh[tid] = g_hWh[(size_t)bidx * NDIM + n0 + tid];
    s_v[tid]   = v[n0 + tid];
  }
  asm volatile("cp.async.wait_group 2;\n" ::: "memory");   // tile 0 arrived
  __syncthreads();
  cvt_tile(dynsm, smb, 0, tid);                            // fp16 buf 0

  for (int kt = 0; kt < KT; kt++) {
    if (kt < KT - 3)
      asm volatile("cp.async.wait_group 1;\n" ::: "memory");  // tile kt+1 in
    else
      asm volatile("cp.async.wait_group 0;\n" ::: "memory");
    __syncthreads();   // orders: STS(kt)→LDSM ; frees A32 slot kt%3, B slot kt&3... 

    if (kt + 3 < KT) load_group(smb, Ag, Bg, kt + 3, tid);
    if (kt + 1 < KT) cvt_tile(dynsm, smb, kt + 1, tid);

    const uint32_t aStg = (uint32_t)(kt & 1) * A16_STG;
    const uint32_t bStg = (uint32_t)(kt & 3) * B_STG;
    #pragma unroll
    for (int ks = 0; ks < 2; ks++) {
      const uint32_t kByte = (uint32_t)(ks * 32);
      uint32_t a[2][4];
      #pragma unroll
      for (int mf = 0; mf < 2; mf++)
        ldsm4(a[mf][0], a[mf][1], a[mf][2], a[mf][3], aOff[mf] + aStg + kByte);
      uint32_t b[8][2];
      #pragma unroll
      for (int nfp = 0; nfp < 4; nfp++)
        ldsm4(b[nfp * 2][0], b[nfp * 2][1], b[nfp * 2 + 1][0], b[nfp * 2 + 1][1],
              bOff[nfp] + bStg + kByte);
      #pragma unroll
      for (int mf = 0; mf < 2; mf++)
        #pragma unroll
        for (int nf = 0; nf < 8; nf++)
          mma16(acc[mf][nf], a[mf], b[nf]);
    }
  }
  __syncthreads();

  // ---------------- epilogue: + hWh, tanh, dot v, reduce over this n-tile
  float p[2][2] = {{0.f, 0.f}, {0.f, 0.f}};
  #pragma unroll
  for (int mf = 0; mf < 2; mf++)
    #pragma unroll
    for (int nf = 0; nf < 8; nf++)
      #pragma unroll
      for (int e = 0; e < 4; e++) {
        const int nl = wn * 64 + nf * 8 + qp * 2 + (e & 1);
        const float en = tanhf(acc[mf][nf][e] + s_hwh[nl]);
        p[mf][e >> 1] += en * s_v[nl];
      }
  #pragma unroll
  for (int mf = 0; mf < 2; mf++)
    #pragma unroll
    for (int h = 0; h < 2; h++) {
      float x = p[mf][h];
      x += __shfl_xor_sync(0xffffffffu, x, 1);
      x += __shfl_xor_sync(0xffffffffu, x, 2);
      if (qp == 0) s_red[wn * BM + wm * 32 + mf * 16 + h * 8 + grp] = x;
    }
  __syncthreads();
  if (tid < BM)
    g_part[(size_t)blockIdx.x * (BDIM * SDIM) + row0 + tid] =
        s_red[tid] + s_red[BM + tid];
}

// ------------------------------------------ kernel 3: mask + softmax(S)
__global__ void softmax_kernel(const int* __restrict__ mask,
                               float* __restrict__ out) {
  const int bq = blockIdx.x;
  const int tid = threadIdx.x;
  float loc[8];
  float mx = -1e30f;
  #pragma unroll
  for (int i = 0; i < 8; i++) {
    const long long idx = (long long)bq * SDIM + i * 256 + tid;
    float sc = 0.0f;
    #pragma unroll
    for (int j = 0; j < 8; j++) sc += g_part[(long long)j * (BDIM * SDIM) + idx];
    if (mask[idx] == 0) sc = -1e9f;
    loc[i] = sc;
    mx = fmaxf(mx, sc);
  }
  __shared__ float sm[8];
  #pragma unroll
  for (int o = 16; o > 0; o >>= 1) mx = fmaxf(mx, __shfl_xor_sync(~0u, mx, o));
  if ((tid & 31) == 0) sm[tid >> 5] = mx;
  __syncthreads();
  if (tid < 32) {
    float t = (tid < 8) ? sm[tid] : -1e30f;
    #pragma unroll
    for (int o = 4; o > 0; o >>= 1) t = fmaxf(t, __shfl_xor_sync(~0u, t, o));
    if (tid == 0) sm[0] = t;
  }
  __syncthreads();
  mx = sm[0];

  float sum = 0.0f;
  #pragma unroll
  for (int i = 0; i < 8; i++) { loc[i] = expf(loc[i] - mx); sum += loc[i]; }
  __shared__ float ss[8];
  #pragma unroll
  for (int o = 16; o > 0; o >>= 1) sum += __shfl_xor_sync(~0u, sum, o);
  if ((tid & 31) == 0) ss[tid >> 5] = sum;
  __syncthreads();
  if (tid < 32) {
    float t = (tid < 8) ? ss[tid] : 0.0f;
    #pragma unroll
    for (int o = 4; o > 0; o >>= 1) t += __shfl_xor_sync(~0u, t, o);
    if (tid == 0) ss[0] = t;
  }
  __syncthreads();
  const float inv = 1.0f / ss[0];
  #pragma unroll
  for (int i = 0; i < 8; i++)
    out[(long long)bq * SDIM + i * 256 + tid] = loc[i] * inv;
}

// ----------------------------------------------------------------- launch
extern "C" void kernel_launch(void* const* d_in, const int* in_sizes, int n_in,
                              void* d_out, int out_size) {
  const float* hidden = nullptr;
  const float* enc    = nullptr;
  const int*   mask   = nullptr;
  const float* W      = nullptr;
  const float* b_attn = nullptr;
  const float* v      = nullptr;

  for (int pass = 0; pass < 2; pass++) {      // elements, then bytes
    const long long mul = (pass == 0) ? 1LL : 4LL;
    hidden = enc = W = b_attn = v = nullptr; mask = nullptr;
    for (int i = 0; i < n_in; i++) {
      const long long sz = (long long)in_sizes[i];
      if      (sz == 65536LL * mul)     hidden = (const float*)d_in[i];
      else if (sz == 268435456LL * mul) enc    = (const float*)d_in[i];
      else if (sz == 131072LL * mul)    mask   = (const int*)  d_in[i];
      else if (sz == 3145728LL * mul)   W      = (const float*)d_in[i];
      else if (sz == 1024LL * mul) {
        if (!b_attn) b_attn = (const float*)d_in[i];
        else         v      = (const float*)d_in[i];
      }
    }
    if (hidden && enc && mask && W && b_attn && v) break;
  }
  if (!hidden || !enc || !mask || !W || !b_attn || !v) {
    hidden = (const float*)d_in[0];
    enc    = (const float*)d_in[1];
    mask   = (const int*)  d_in[2];
    W      = (const float*)d_in[3];
    b_attn = (const float*)d_in[4];
    v      = (const float*)d_in[5];
  }
  float* out = (float*)d_out;   // (B,S) float32

  static bool attr_set = false;
  if (!attr_set) {
    cudaFuncSetAttribute(energy_fp16_kernel,
                         cudaFuncAttributeMaxDynamicSharedMemorySize, SMEM_TOTAL);
    attr_set = true;
  }

  wt_kernel<<<dim3(32, 64), dim3(32, 8)>>>(W);
  hwh_kernel<<<dim3(4, BDIM), 256>>>(hidden, W, b_attn);
  energy_fp16_kernel<<<dim3(8, 1024), 256, SMEM_TOTAL>>>(enc, v);
  softmax_kernel<<<BDIM, 256>>>(mask, out);
}

// round 12
// speedup vs baseline: 2.0326x; 2.0326x over previous
#include <cuda_runtime.h>
#include <cuda_fp16.h>
#include <cstdint>
#include <math.h>

#define BDIM 64
#define SDIM 2048
#define HDIM 1024
#define KDIM 2048   // 2H (contraction)
#define NDIM 1024   // H  (energy dim)

#define BM 128
#define BN 128
#define BK 32        // halves per k-tile
#define PADH 40      // row pitch in halves (80B: 16B multiple, conflict-free LDSM)
#define NST 4        // cp.async pipeline stages
#define STAGE_B (BM * PADH * 2)   // bytes per (A or B) stage = 10240

// ---- device scratch (allocation-free rule: __device__ globals) ----
__device__ float  g_hWh[BDIM * NDIM];               // hidden@Wh + b_attn
__device__ float  g_part[8 * BDIM * SDIM];          // per-nTile partial scores
__device__ __half g_encH[(size_t)BDIM * SDIM * KDIM];  // compacted enc fp16
__device__ __half g_WhT[(size_t)NDIM * KDIM];          // We^T fp16 [N][K]
__device__ int    g_idx[BDIM * SDIM];               // compacted s' -> s
__device__ int    g_cnt[BDIM];                      // surviving rows per batch

// ---------------------------------------------------------------- helpers
__device__ __forceinline__ void cpa16(void* s, const void* g) {
  uint32_t sa = (uint32_t)__cvta_generic_to_shared(s);
  asm volatile("cp.async.cg.shared.global [%0], [%1], 16;\n" :: "r"(sa), "l"(g));
}
__device__ __forceinline__ uint32_t smem_u32(const void* p) {
  uint32_t a;
  asm("{ .reg .u64 t; cvta.to.shared.u64 t, %1; cvt.u32.u64 %0, t; }" : "=r"(a) : "l"(p));
  return a;
}
__device__ __forceinline__ void mma16(float* d, const uint32_t* a, const uint32_t* b) {
  asm volatile(
    "mma.sync.aligned.m16n8k16.row.col.f32.f16.f16.f32 "
    "{%0,%1,%2,%3}, {%4,%5,%6,%7}, {%8,%9}, {%0,%1,%2,%3};\n"
    : "+f"(d[0]), "+f"(d[1]), "+f"(d[2]), "+f"(d[3])
    : "r"(a[0]), "r"(a[1]), "r"(a[2]), "r"(a[3]), "r"(b[0]), "r"(b[1]));
}
__device__ __forceinline__ void ldsm4(uint32_t& r0, uint32_t& r1,
                                      uint32_t& r2, uint32_t& r3, uint32_t addr) {
  asm volatile("ldmatrix.sync.aligned.m8n8.x4.shared.b16 {%0,%1,%2,%3}, [%4];"
               : "=r"(r0), "=r"(r1), "=r"(r2), "=r"(r3) : "r"(addr));
}

// --------------------------- kernel A: per-batch mask compaction (scan)
__global__ void compact_kernel(const int* __restrict__ mask) {
  const int b = blockIdx.x;        // 64
  const int tid = threadIdx.x;     // 256, each handles 8 consecutive s
  __shared__ int wsum[8];
  int m[8];
  int c = 0;
  const int base = b * SDIM + tid * 8;
  #pragma unroll
  for (int i = 0; i < 8; i++) { m[i] = mask[base + i]; c += (m[i] != 0); }
  // inclusive warp scan of per-thread counts
  int inc = c;
  #pragma unroll
  for (int o = 1; o < 32; o <<= 1) {
    int y = __shfl_up_sync(0xffffffffu, inc, o);
    if ((tid & 31) >= o) inc += y;
  }
  if ((tid & 31) == 31) wsum[tid >> 5] = inc;
  __syncthreads();
  if (tid < 8) {
    int v = wsum[tid];
    #pragma unroll
    for (int o = 1; o < 8; o <<= 1) {
      int y = __shfl_up_sync(0x000000ffu, v, o);
      if (tid >= o) v += y;
    }
    wsum[tid] = v;   // inclusive warp-block sums
  }
  __syncthreads();
  int pos = (inc - c) + ((tid >= 32) ? wsum[(tid >> 5) - 1] : 0);
  #pragma unroll
  for (int i = 0; i < 8; i++)
    if (m[i] != 0) g_idx[b * SDIM + (pos++)] = tid * 8 + i;
  if (tid == 255) g_cnt[b] = wsum[7];
}

// ------------- kernel B: gather surviving enc rows -> compacted fp16
__global__ void enc2h_gather(const float4* __restrict__ enc4) {
  const int b  = blockIdx.y;
  const int sp = blockIdx.x;                 // compacted row
  if (sp >= g_cnt[b]) return;
  const int s = g_idx[b * SDIM + sp];
  const float4* src = enc4 + ((size_t)b * SDIM + s) * (KDIM / 4);
  __half2* dst = (__half2*)(g_encH + ((size_t)b * SDIM + sp) * KDIM);
  for (int i = threadIdx.x; i < KDIM / 4; i += 256) {
    float4 x = src[i];
    dst[i * 2]     = __floats2half2_rn(x.x, x.y);
    dst[i * 2 + 1] = __floats2half2_rn(x.z, x.w);
  }
}

// ----------------------- kernel 0: WhT[n][k] = fp16(W[H+k][n]) transpose
__global__ void wt_kernel(const float* __restrict__ W) {
  __shared__ float t[32][33];
  const int n0 = blockIdx.x * 32;
  const int k0 = blockIdx.y * 32;
  const int tx = threadIdx.x, ty = threadIdx.y;   // 32 x 8
  #pragma unroll
  for (int i = 0; i < 4; i++)
    t[ty + i * 8][tx] = W[(size_t)(HDIM + k0 + ty + i * 8) * NDIM + n0 + tx];
  __syncthreads();
  #pragma unroll
  for (int i = 0; i < 4; i++)
    g_WhT[(size_t)(n0 + ty + i * 8) * KDIM + k0 + tx] =
        __float2half_rn(t[tx][ty + i * 8]);
}

// ------------------------------------------------- kernel 1: hWh + b_attn
__global__ void hwh_kernel(const float* __restrict__ hidden,
                           const float* __restrict__ W,
                           const float* __restrict__ b_attn) {
  const int n = blockIdx.x * 256 + threadIdx.x;
  const int b = blockIdx.y;
  const float* hrow = hidden + (long long)b * HDIM;
  float a0 = 0.f, a1 = 0.f, a2 = 0.f, a3 = 0.f;   // break FMA dep chain
  for (int h = 0; h < HDIM; h += 4) {
    a0 = fmaf(hrow[h    ], W[(long long)(h    ) * NDIM + n], a0);
    a1 = fmaf(hrow[h + 1], W[(long long)(h + 1) * NDIM + n], a1);
    a2 = fmaf(hrow[h + 2], W[(long long)(h + 2) * NDIM + n], a2);
    a3 = fmaf(hrow[h + 3], W[(long long)(h + 3) * NDIM + n], a3);
  }
  g_hWh[(long long)b * NDIM + n] = (a0 + a1) + (a2 + a3) + b_attn[n];
}

// ------------------------------------------------ tile loader (cp.async)
__device__ __forceinline__ void load_tile(__half (*As)[PADH], __half (*Bs)[PADH],
                                          const __half* Ag, const __half* Bg,
                                          int kh, int tid) {
  #pragma unroll
  for (int i = 0; i < 2; i++) {
    int c = tid * 2 + i;
    int r = c >> 2, q = c & 3;
    cpa16(&As[r][q * 8], Ag + (size_t)r * KDIM + kh + q * 8);
    cpa16(&Bs[r][q * 8], Bg + (size_t)r * KDIM + kh + q * 8);
  }
  asm volatile("cp.async.commit_group;\n" ::: "memory");
}

// ------------- kernel 2: fused E = enc@We (fp16 MMA) ; p = v·tanh(E+hWh)
// grid: (8 n-tiles, 64 batches x 16 m-tiles) — per-batch compacted rows
__global__ __launch_bounds__(256, 2)
void energy_fp16_kernel(const float* __restrict__ v) {
  const int b    = blockIdx.y >> 4;       // batch
  const int tile = blockIdx.y & 15;       // m-tile within batch (compacted)
  const int cnt  = g_cnt[b];
  if (tile * BM >= cnt) return;           // dead tile: exit before barriers

  extern __shared__ __align__(16) char dynsm[];
  __half (*As)[BM][PADH] = reinterpret_cast<__half(*)[BM][PADH]>(dynsm);
  __half (*Bs)[BM][PADH] = reinterpret_cast<__half(*)[BM][PADH]>(dynsm + NST * STAGE_B);
  float* s_hwh = (float*)(dynsm + 2 * NST * STAGE_B);
  float* s_v   = s_hwh + BN;
  float* s_red = s_v + BN;                 // [2][BM]

  const int tid  = threadIdx.x;
  const int lane = tid & 31;
  const int wid  = tid >> 5;
  const int wm   = wid & 3;    // warp grid 4(M) x 2(N)
  const int wn   = wid >> 2;
  const int grp  = lane >> 2;  // 0..7
  const int qp   = lane & 3;   // 0..3

  const int n0 = blockIdx.x * BN;          // x fastest => L2 reuse of A
  const int row0c = tile * BM;             // compacted row base within batch

  const __half* Ag = g_encH + ((size_t)b * SDIM + row0c) * KDIM;
  const __half* Bg = g_WhT + (size_t)n0 * KDIM;

  // ---- ldmatrix per-lane byte offsets (within one stage) ----
  const int l8 = lane & 7;
  const int lm = lane >> 3;
  uint32_t aOff[2];
  #pragma unroll
  for (int mf = 0; mf < 2; mf++) {
    const int row = wm * 32 + mf * 16 + l8 + (lm & 1) * 8;
    const int col = (lm >> 1) * 8;
    aOff[mf] = (uint32_t)((row * PADH + col) * 2);
  }
  uint32_t bOff[4];
  #pragma unroll
  for (int nfp = 0; nfp < 4; nfp++) {
    const int row = wn * 64 + nfp * 16 + l8 + (lm >> 1) * 8;
    const int col = (lm & 1) * 8;
    bOff[nfp] = (uint32_t)((row * PADH + col) * 2);
  }
  const uint32_t aB0 = smem_u32(&As[0][0][0]);
  const uint32_t bB0 = smem_u32(&Bs[0][0][0]);

  float acc[2][8][4];
  #pragma unroll
  for (int i = 0; i < 2; i++)
    #pragma unroll
    for (int j = 0; j < 8; j++)
      #pragma unroll
      for (int e = 0; e < 4; e++) acc[i][j][e] = 0.f;

  const int KT = KDIM / BK;  // 64
  load_tile(As[0], Bs[0], Ag, Bg, 0 * BK, tid);
  load_tile(As[1], Bs[1], Ag, Bg, 1 * BK, tid);
  load_tile(As[2], Bs[2], Ag, Bg, 2 * BK, tid);
  if (tid < BN) {
    s_hwh[tid] = g_hWh[(size_t)b * NDIM + n0 + tid];
    s_v[tid]   = v[n0 + tid];
  }

  for (int kt = 0; kt < KT; kt++) {
    const int cur = kt & 3;
    if (kt < KT - 2)
      asm volatile("cp.async.wait_group 2;\n" ::: "memory");
    else if (kt == KT - 2)
      asm volatile("cp.async.wait_group 1;\n" ::: "memory");
    else
      asm volatile("cp.async.wait_group 0;\n" ::: "memory");
    __syncthreads();   // stage `cur` visible; stage (kt+3)%4 free (read in kt-1)

    const int ktn = kt + 3;                 // refill overlaps compute below
    if (ktn < KT) {
      const int sn = ktn & 3;
      load_tile(As[sn], Bs[sn], Ag, Bg, ktn * BK, tid);
    }

    const uint32_t aBase = aB0 + (uint32_t)cur * STAGE_B;
    const uint32_t bBase = bB0 + (uint32_t)cur * STAGE_B;
    #pragma unroll
    for (int ks = 0; ks < 2; ks++) {
      const uint32_t kByte = (uint32_t)(ks * 16 * 2);
      uint32_t a[2][4];
      #pragma unroll
      for (int mf = 0; mf < 2; mf++)
        ldsm4(a[mf][0], a[mf][1], a[mf][2], a[mf][3], aBase + aOff[mf] + kByte);
      uint32_t bb[8][2];
      #pragma unroll
      for (int nfp = 0; nfp < 4; nfp++)
        ldsm4(bb[nfp * 2][0], bb[nfp * 2][1], bb[nfp * 2 + 1][0], bb[nfp * 2 + 1][1],
              bBase + bOff[nfp] + kByte);
      #pragma unroll
      for (int mf = 0; mf < 2; mf++)
        #pragma unroll
        for (int nf = 0; nf < 8; nf++)
          mma16(acc[mf][nf], a[mf], bb[nf]);
    }
  }
  __syncthreads();

  // ---------------- epilogue: + hWh, tanh, dot v, reduce over this n-tile
  float p[2][2] = {{0.f, 0.f}, {0.f, 0.f}};
  #pragma unroll
  for (int mf = 0; mf < 2; mf++)
    #pragma unroll
    for (int nf = 0; nf < 8; nf++)
      #pragma unroll
      for (int e = 0; e < 4; e++) {
        // C frag: d0:(g,2t) d1:(g,2t+1) d2:(g+8,2t) d3:(g+8,2t+1)
        const int nl = wn * 64 + nf * 8 + qp * 2 + (e & 1);
        const float en = tanhf(acc[mf][nf][e] + s_hwh[nl]);
        p[mf][e >> 1] += en * s_v[nl];
      }
  #pragma unroll
  for (int mf = 0; mf < 2; mf++)
    #pragma unroll
    for (int h = 0; h < 2; h++) {
      float x = p[mf][h];
      x += __shfl_xor_sync(0xffffffffu, x, 1);
      x += __shfl_xor_sync(0xffffffffu, x, 2);
      if (qp == 0) s_red[wn * BM + wm * 32 + mf * 16 + h * 8 + grp] = x;
    }
  __syncthreads();
  if (tid < BM) {
    const int sp = row0c + tid;
    if (sp < cnt) {                        // skip padding rows
      const int s = g_idx[b * SDIM + sp];  // scatter to original position
      g_part[(size_t)blockIdx.x * (BDIM * SDIM) + (size_t)b * SDIM + s] =
          s_red[tid] + s_red[BM + tid];
    }
  }
}

// ------------------------------------------ kernel 3: mask + softmax(S)
__global__ void softmax_kernel(const int* __restrict__ mask,
                               float* __restrict__ out) {
  const int bq = blockIdx.x;
  const int tid = threadIdx.x;
  float loc[8];
  float mx = -1e30f;
  #pragma unroll
  for (int i = 0; i < 8; i++) {
    const long long idx = (long long)bq * SDIM + i * 256 + tid;
    float sc = 0.0f;
    #pragma unroll
    for (int j = 0; j < 8; j++) sc += g_part[(long long)j * (BDIM * SDIM) + idx];
    if (mask[idx] == 0) sc = -1e9f;        // masked: computed value irrelevant
    loc[i] = sc;
    mx = fmaxf(mx, sc);
  }
  __shared__ float sm[8];
  #pragma unroll
  for (int o = 16; o > 0; o >>= 1) mx = fmaxf(mx, __shfl_xor_sync(~0u, mx, o));
  if ((tid & 31) == 0) sm[tid >> 5] = mx;
  __syncthreads();
  if (tid < 32) {
    float t = (tid < 8) ? sm[tid] : -1e30f;
    #pragma unroll
    for (int o = 4; o > 0; o >>= 1) t = fmaxf(t, __shfl_xor_sync(~0u, t, o));
    if (tid == 0) sm[0] = t;
  }
  __syncthreads();
  mx = sm[0];

  float sum = 0.0f;
  #pragma unroll
  for (int i = 0; i < 8; i++) { loc[i] = expf(loc[i] - mx); sum += loc[i]; }
  __shared__ float ss[8];
  #pragma unroll
  for (int o = 16; o > 0; o >>= 1) sum += __shfl_xor_sync(~0u, sum, o);
  if ((tid & 31) == 0) ss[tid >> 5] = sum;
  __syncthreads();
  if (tid < 32) {
    float t = (tid < 8) ? ss[tid] : 0.0f;
    #pragma unroll
    for (int o = 4; o > 0; o >>= 1) t += __shfl_xor_sync(~0u, t, o);
    if (tid == 0) ss[0] = t;
  }
  __syncthreads();
  const float inv = 1.0f / ss[0];
  #pragma unroll
  for (int i = 0; i < 8; i++)
    out[(long long)bq * SDIM + i * 256 + tid] = loc[i] * inv;
}

// ----------------------------------------------------------------- launch
extern "C" void kernel_launch(void* const* d_in, const int* in_sizes, int n_in,
                              void* d_out, int out_size) {
  const float* hidden = nullptr;
  const float* enc    = nullptr;
  const int*   mask   = nullptr;
  const float* W      = nullptr;
  const float* b_attn = nullptr;
  const float* v      = nullptr;

  for (int pass = 0; pass < 2; pass++) {      // elements, then bytes
    const long long mul = (pass == 0) ? 1LL : 4LL;
    hidden = enc = W = b_attn = v = nullptr; mask = nullptr;
    for (int i = 0; i < n_in; i++) {
      const long long sz = (long long)in_sizes[i];
      if      (sz == 65536LL * mul)     hidden = (const float*)d_in[i];
      else if (sz == 268435456LL * mul) enc    = (const float*)d_in[i];
      else if (sz == 131072LL * mul)    mask   = (const int*)  d_in[i];
      else if (sz == 3145728LL * mul)   W      = (const float*)d_in[i];
      else if (sz == 1024LL * mul) {
        if (!b_attn) b_attn = (const float*)d_in[i];
        else         v      = (const float*)d_in[i];
      }
    }
    if (hidden && enc && mask && W && b_attn && v) break;
  }
  if (!hidden || !enc || !mask || !W || !b_attn || !v) {
    hidden = (const float*)d_in[0];
    enc    = (const float*)d_in[1];
    mask   = (const int*)  d_in[2];
    W      = (const float*)d_in[3];
    b_attn = (const float*)d_in[4];
    v      = (const float*)d_in[5];
  }
  float* out = (float*)d_out;   // (B,S) float32

  const int smem_bytes = 2 * NST * STAGE_B + (2 * BN + 2 * BM) * 4;  // 84032
  static bool attr_set = false;
  if (!attr_set) {
    cudaFuncSetAttribute(energy_fp16_kernel,
                         cudaFuncAttributeMaxDynamicSharedMemorySize, smem_bytes);
    attr_set = true;
  }

  compact_kernel<<<BDIM, 256>>>(mask);
  enc2h_gather<<<dim3(SDIM, BDIM), 256>>>((const float4*)enc);
  wt_kernel<<<dim3(32, 64), dim3(32, 8)>>>(W);
  hwh_kernel<<<dim3(4, BDIM), 256>>>(hidden, W, b_attn);
  energy_fp16_kernel<<<dim3(8, BDIM * 16), 256, smem_bytes>>>(v);
  softmax_kernel<<<BDIM, 256>>>(mask, out);
}

// round 13
// speedup vs baseline: 2.1317x; 1.0487x over previous
#include <cuda_runtime.h>
#include <cuda_fp16.h>
#include <cstdint>
#include <math.h>

#define BDIM 64
#define SDIM 2048
#define HDIM 1024
#define KDIM 2048   // 2H (contraction)
#define NDIM 1024   // H  (energy dim)

#define BM 128
#define BN 128
#define BK 32        // halves per k-tile
#define PADH 40      // row pitch in halves (80B: 16B multiple, conflict-free LDSM)
#define NST 4        // cp.async pipeline stages
#define STAGE_B (BM * PADH * 2)   // bytes per (A or B) stage = 10240

// ---- device scratch (allocation-free rule: __device__ globals) ----
__device__ float  g_hWh[BDIM * NDIM];               // hidden@Wh + b_attn
__device__ float  g_hWhP[8][BDIM * NDIM];           // split-K partials
__device__ float  g_part[8 * BDIM * SDIM];          // per-nTile partial scores
__device__ __half g_encH[(size_t)BDIM * SDIM * KDIM];  // compacted enc fp16
__device__ __half g_WhT[(size_t)NDIM * KDIM];          // We^T fp16 [N][K]
__device__ int    g_idx[BDIM * SDIM];               // compacted s' -> s
__device__ int    g_cnt[BDIM];                      // surviving rows per batch

// ---------------------------------------------------------------- helpers
__device__ __forceinline__ void cpa16(void* s, const void* g) {
  uint32_t sa = (uint32_t)__cvta_generic_to_shared(s);
  asm volatile("cp.async.cg.shared.global [%0], [%1], 16;\n" :: "r"(sa), "l"(g));
}
__device__ __forceinline__ uint32_t smem_u32(const void* p) {
  uint32_t a;
  asm("{ .reg .u64 t; cvta.to.shared.u64 t, %1; cvt.u32.u64 %0, t; }" : "=r"(a) : "l"(p));
  return a;
}
__device__ __forceinline__ void mma16(float* d, const uint32_t* a, const uint32_t* b) {
  asm volatile(
    "mma.sync.aligned.m16n8k16.row.col.f32.f16.f16.f32 "
    "{%0,%1,%2,%3}, {%4,%5,%6,%7}, {%8,%9}, {%0,%1,%2,%3};\n"
    : "+f"(d[0]), "+f"(d[1]), "+f"(d[2]), "+f"(d[3])
    : "r"(a[0]), "r"(a[1]), "r"(a[2]), "r"(a[3]), "r"(b[0]), "r"(b[1]));
}
__device__ __forceinline__ void ldsm4(uint32_t& r0, uint32_t& r1,
                                      uint32_t& r2, uint32_t& r3, uint32_t addr) {
  asm volatile("ldmatrix.sync.aligned.m8n8.x4.shared.b16 {%0,%1,%2,%3}, [%4];"
               : "=r"(r0), "=r"(r1), "=r"(r2), "=r"(r3) : "r"(addr));
}

// --------------------------- kernel A: per-batch mask compaction (scan)
__global__ void compact_kernel(const int* __restrict__ mask) {
  const int b = blockIdx.x;        // 64
  const int tid = threadIdx.x;     // 256, each handles 8 consecutive s
  __shared__ int wsum[8];
  int m[8];
  int c = 0;
  const int base = b * SDIM + tid * 8;
  #pragma unroll
  for (int i = 0; i < 8; i++) { m[i] = mask[base + i]; c += (m[i] != 0); }
  int inc = c;
  #pragma unroll
  for (int o = 1; o < 32; o <<= 1) {
    int y = __shfl_up_sync(0xffffffffu, inc, o);
    if ((tid & 31) >= o) inc += y;
  }
  if ((tid & 31) == 31) wsum[tid >> 5] = inc;
  __syncthreads();
  if (tid < 8) {
    int v = wsum[tid];
    #pragma unroll
    for (int o = 1; o < 8; o <<= 1) {
      int y = __shfl_up_sync(0x000000ffu, v, o);
      if (tid >= o) v += y;
    }
    wsum[tid] = v;
  }
  __syncthreads();
  int pos = (inc - c) + ((tid >= 32) ? wsum[(tid >> 5) - 1] : 0);
  #pragma unroll
  for (int i = 0; i < 8; i++)
    if (m[i] != 0) g_idx[b * SDIM + (pos++)] = tid * 8 + i;
  if (tid == 255) g_cnt[b] = wsum[7];
}

// ------------- kernel B: gather surviving enc rows -> compacted fp16
__global__ void enc2h_gather(const float4* __restrict__ enc4) {
  const int b  = blockIdx.y;
  const int sp = blockIdx.x;                 // compacted row
  if (sp >= g_cnt[b]) return;
  const int s = g_idx[b * SDIM + sp];
  const float4* src = enc4 + ((size_t)b * SDIM + s) * (KDIM / 4);
  __half2* dst = (__half2*)(g_encH + ((size_t)b * SDIM + sp) * KDIM);
  for (int i = threadIdx.x; i < KDIM / 4; i += 256) {
    float4 x = src[i];
    dst[i * 2]     = __floats2half2_rn(x.x, x.y);
    dst[i * 2 + 1] = __floats2half2_rn(x.z, x.w);
  }
}

// ----------------------- kernel 0: WhT[n][k] = fp16(W[H+k][n]) transpose
__global__ void wt_kernel(const float* __restrict__ W) {
  __shared__ float t[32][33];
  const int n0 = blockIdx.x * 32;
  const int k0 = blockIdx.y * 32;
  const int tx = threadIdx.x, ty = threadIdx.y;   // 32 x 8
  #pragma unroll
  for (int i = 0; i < 4; i++)
    t[ty + i * 8][tx] = W[(size_t)(HDIM + k0 + ty + i * 8) * NDIM + n0 + tx];
  __syncthreads();
  #pragma unroll
  for (int i = 0; i < 4; i++)
    g_WhT[(size_t)(n0 + ty + i * 8) * KDIM + k0 + tx] =
        __float2half_rn(t[tx][ty + i * 8]);
}

// ------------------------------- kernel 1a: hWh split-K partials (MLP x8)
__global__ void hwh_part_kernel(const float* __restrict__ hidden,
                                const float* __restrict__ W,
                                const float* __restrict__ b_attn) {
  const int n  = blockIdx.x * 256 + threadIdx.x;   // 4 blocks
  const int b  = blockIdx.y;                       // 64
  const int kz = blockIdx.z;                       // 8 k-splits of 128
  const float* hrow = hidden + (long long)b * HDIM + kz * 128;
  const float* Wp   = W + (size_t)(kz * 128) * NDIM + n;
  float a0 = 0.f, a1 = 0.f, a2 = 0.f, a3 = 0.f;
  #pragma unroll 8
  for (int h = 0; h < 128; h += 4) {
    a0 = fmaf(hrow[h    ], Wp[(size_t)(h    ) * NDIM], a0);
    a1 = fmaf(hrow[h + 1], Wp[(size_t)(h + 1) * NDIM], a1);
    a2 = fmaf(hrow[h + 2], Wp[(size_t)(h + 2) * NDIM], a2);
    a3 = fmaf(hrow[h + 3], Wp[(size_t)(h + 3) * NDIM], a3);
  }
  g_hWhP[kz][b * NDIM + n] =
      (a0 + a1) + (a2 + a3) + ((kz == 0) ? b_attn[n] : 0.f);
}

// ------------------------------- kernel 1b: reduce split-K partials
__global__ void hwh_reduce_kernel() {
  const int i = blockIdx.x * 256 + threadIdx.x;    // 256 blocks
  float s = 0.f;
  #pragma unroll
  for (int j = 0; j < 8; j++) s += g_hWhP[j][i];
  g_hWh[i] = s;
}

// ------------------------------------------------ tile loader (cp.async)
__device__ __forceinline__ void load_tile(__half (*As)[PADH], __half (*Bs)[PADH],
                                          const __half* Ag, const __half* Bg,
                                          int kh, int tid) {
  #pragma unroll
  for (int i = 0; i < 2; i++) {
    int c = tid * 2 + i;
    int r = c >> 2, q = c & 3;
    cpa16(&As[r][q * 8], Ag + (size_t)r * KDIM + kh + q * 8);
    cpa16(&Bs[r][q * 8], Bg + (size_t)r * KDIM + kh + q * 8);
  }
  asm volatile("cp.async.commit_group;\n" ::: "memory");
}

// ------------- kernel 2: fused E = enc@We (fp16 MMA) ; p = v·tanh(E+hWh)
// grid: (8 n-tiles, 64 batches x 16 m-tiles) — per-batch compacted rows
__global__ __launch_bounds__(256, 2)
void energy_fp16_kernel(const float* __restrict__ v) {
  const int b    = blockIdx.y >> 4;       // batch
  const int tile = blockIdx.y & 15;       // m-tile within batch (compacted)
  const int cnt  = g_cnt[b];
  if (tile * BM >= cnt) return;           // dead tile: exit before barriers

  extern __shared__ __align__(16) char dynsm[];
  __half (*As)[BM][PADH] = reinterpret_cast<__half(*)[BM][PADH]>(dynsm);
  __half (*Bs)[BM][PADH] = reinterpret_cast<__half(*)[BM][PADH]>(dynsm + NST * STAGE_B);
  float* s_hwh = (float*)(dynsm + 2 * NST * STAGE_B);
  float* s_v   = s_hwh + BN;
  float* s_red = s_v + BN;                 // [2][BM]

  const int tid  = threadIdx.x;
  const int lane = tid & 31;
  const int wid  = tid >> 5;
  const int wm   = wid & 3;    // warp grid 4(M) x 2(N)
  const int wn   = wid >> 2;
  const int grp  = lane >> 2;  // 0..7
  const int qp   = lane & 3;   // 0..3

  const int n0 = blockIdx.x * BN;          // x fastest => L2 reuse of A
  const int row0c = tile * BM;             // compacted row base within batch

  const __half* Ag = g_encH + ((size_t)b * SDIM + row0c) * KDIM;
  const __half* Bg = g_WhT + (size_t)n0 * KDIM;

  // ---- ldmatrix per-lane byte offsets (within one stage) ----
  const int l8 = lane & 7;
  const int lm = lane >> 3;
  uint32_t aOff[2];
  #pragma unroll
  for (int mf = 0; mf < 2; mf++) {
    const int row = wm * 32 + mf * 16 + l8 + (lm & 1) * 8;
    const int col = (lm >> 1) * 8;
    aOff[mf] = (uint32_t)((row * PADH + col) * 2);
  }
  uint32_t bOff[4];
  #pragma unroll
  for (int nfp = 0; nfp < 4; nfp++) {
    const int row = wn * 64 + nfp * 16 + l8 + (lm >> 1) * 8;
    const int col = (lm & 1) * 8;
    bOff[nfp] = (uint32_t)((row * PADH + col) * 2);
  }
  const uint32_t aB0 = smem_u32(&As[0][0][0]);
  const uint32_t bB0 = smem_u32(&Bs[0][0][0]);

  float acc[2][8][4];
  #pragma unroll
  for (int i = 0; i < 2; i++)
    #pragma unroll
    for (int j = 0; j < 8; j++)
      #pragma unroll
      for (int e = 0; e < 4; e++) acc[i][j][e] = 0.f;

  const int KT = KDIM / BK;  // 64
  load_tile(As[0], Bs[0], Ag, Bg, 0 * BK, tid);
  load_tile(As[1], Bs[1], Ag, Bg, 1 * BK, tid);
  load_tile(As[2], Bs[2], Ag, Bg, 2 * BK, tid);
  if (tid < BN) {
    s_hwh[tid] = g_hWh[(size_t)b * NDIM + n0 + tid];
    s_v[tid]   = v[n0 + tid];
  }

  for (int kt = 0; kt < KT; kt++) {
    const int cur = kt & 3;
    if (kt < KT - 2)
      asm volatile("cp.async.wait_group 2;\n" ::: "memory");
    else if (kt == KT - 2)
      asm volatile("cp.async.wait_group 1;\n" ::: "memory");
    else
      asm volatile("cp.async.wait_group 0;\n" ::: "memory");
    __syncthreads();   // stage `cur` visible; stage (kt+3)%4 free (read in kt-1)

    const int ktn = kt + 3;                 // refill overlaps compute below
    if (ktn < KT) {
      const int sn = ktn & 3;
      load_tile(As[sn], Bs[sn], Ag, Bg, ktn * BK, tid);
    }

    const uint32_t aBase = aB0 + (uint32_t)cur * STAGE_B;
    const uint32_t bBase = bB0 + (uint32_t)cur * STAGE_B;
    #pragma unroll
    for (int ks = 0; ks < 2; ks++) {
      const uint32_t kByte = (uint32_t)(ks * 16 * 2);
      uint32_t a[2][4];
      #pragma unroll
      for (int mf = 0; mf < 2; mf++)
        ldsm4(a[mf][0], a[mf][1], a[mf][2], a[mf][3], aBase + aOff[mf] + kByte);
      uint32_t bb[8][2];
      #pragma unroll
      for (int nfp = 0; nfp < 4; nfp++)
        ldsm4(bb[nfp * 2][0], bb[nfp * 2][1], bb[nfp * 2 + 1][0], bb[nfp * 2 + 1][1],
              bBase + bOff[nfp] + kByte);
      #pragma unroll
      for (int mf = 0; mf < 2; mf++)
        #pragma unroll
        for (int nf = 0; nf < 8; nf++)
          mma16(acc[mf][nf], a[mf], bb[nf]);
    }
  }
  __syncthreads();

  // ---------------- epilogue: + hWh, tanh, dot v, reduce over this n-tile
  float p[2][2] = {{0.f, 0.f}, {0.f, 0.f}};
  #pragma unroll
  for (int mf = 0; mf < 2; mf++)
    #pragma unroll
    for (int nf = 0; nf < 8; nf++)
      #pragma unroll
      for (int e = 0; e < 4; e++) {
        const int nl = wn * 64 + nf * 8 + qp * 2 + (e & 1);
        const float en = tanhf(acc[mf][nf][e] + s_hwh[nl]);
        p[mf][e >> 1] += en * s_v[nl];
      }
  #pragma unroll
  for (int mf = 0; mf < 2; mf++)
    #pragma unroll
    for (int h = 0; h < 2; h++) {
      float x = p[mf][h];
      x += __shfl_xor_sync(0xffffffffu, x, 1);
      x += __shfl_xor_sync(0xffffffffu, x, 2);
      if (qp == 0) s_red[wn * BM + wm * 32 + mf * 16 + h * 8 + grp] = x;
    }
  __syncthreads();
  if (tid < BM) {
    const int sp = row0c + tid;
    if (sp < cnt) {                        // skip padding rows
      const int s = g_idx[b * SDIM + sp];  // scatter to original position
      g_part[(size_t)blockIdx.x * (BDIM * SDIM) + (size_t)b * SDIM + s] =
          s_red[tid] + s_red[BM + tid];
    }
  }
}

// ------------------------------------------ kernel 3: mask + softmax(S)
__global__ void softmax_kernel(const int* __restrict__ mask,
                               float* __restrict__ out) {
  const int bq = blockIdx.x;
  const int tid = threadIdx.x;
  float loc[8];
  float mx = -1e30f;
  #pragma unroll
  for (int i = 0; i < 8; i++) {
    const long long idx = (long long)bq * SDIM + i * 256 + tid;
    float sc = 0.0f;
    #pragma unroll
    for (int j = 0; j < 8; j++) sc += g_part[(long long)j * (BDIM * SDIM) + idx];
    if (mask[idx] == 0) sc = -1e9f;
    loc[i] = sc;
    mx = fmaxf(mx, sc);
  }
  __shared__ float sm[8];
  #pragma unroll
  for (int o = 16; o > 0; o >>= 1) mx = fmaxf(mx, __shfl_xor_sync(~0u, mx, o));
  if ((tid & 31) == 0) sm[tid >> 5] = mx;
  __syncthreads();
  if (tid < 32) {
    float t = (tid < 8) ? sm[tid] : -1e30f;
    #pragma unroll
    for (int o = 4; o > 0; o >>= 1) t = fmaxf(t, __shfl_xor_sync(~0u, t, o));
    if (tid == 0) sm[0] = t;
  }
  __syncthreads();
  mx = sm[0];

  float sum = 0.0f;
  #pragma unroll
  for (int i = 0; i < 8; i++) { loc[i] = expf(loc[i] - mx); sum += loc[i]; }
  __shared__ float ss[8];
  #pragma unroll
  for (int o = 16; o > 0; o >>= 1) sum += __shfl_xor_sync(~0u, sum, o);
  if ((tid & 31) == 0) ss[tid >> 5] = sum;
  __syncthreads();
  if (tid < 32) {
    float t = (tid < 8) ? ss[tid] : 0.0f;
    #pragma unroll
    for (int o = 4; o > 0; o >>= 1) t += __shfl_xor_sync(~0u, t, o);
    if (tid == 0) ss[0] = t;
  }
  __syncthreads();
  const float inv = 1.0f / ss[0];
  #pragma unroll
  for (int i = 0; i < 8; i++)
    out[(long long)bq * SDIM + i * 256 + tid] = loc[i] * inv;
}

// ----------------------------------------------------------------- launch
extern "C" void kernel_launch(void* const* d_in, const int* in_sizes, int n_in,
                              void* d_out, int out_size) {
  const float* hidden = nullptr;
  const float* enc    = nullptr;
  const int*   mask   = nullptr;
  const float* W      = nullptr;
  const float* b_attn = nullptr;
  const float* v      = nullptr;

  for (int pass = 0; pass < 2; pass++) {      // elements, then bytes
    const long long mul = (pass == 0) ? 1LL : 4LL;
    hidden = enc = W = b_attn = v = nullptr; mask = nullptr;
    for (int i = 0; i < n_in; i++) {
      const long long sz = (long long)in_sizes[i];
      if      (sz == 65536LL * mul)     hidden = (const float*)d_in[i];
      else if (sz == 268435456LL * mul) enc    = (const float*)d_in[i];
      else if (sz == 131072LL * mul)    mask   = (const int*)  d_in[i];
      else if (sz == 3145728LL * mul)   W      = (const float*)d_in[i];
      else if (sz == 1024LL * mul) {
        if (!b_attn) b_attn = (const float*)d_in[i];
        else         v      = (const float*)d_in[i];
      }
    }
    if (hidden && enc && mask && W && b_attn && v) break;
  }
  if (!hidden || !enc || !mask || !W || !b_attn || !v) {
    hidden = (const float*)d_in[0];
    enc    = (const float*)d_in[1];
    mask   = (const int*)  d_in[2];
    W      = (const float*)d_in[3];
    b_attn = (const float*)d_in[4];
    v      = (const float*)d_in[5];
  }
  float* out = (float*)d_out;   // (B,S) float32

  const int smem_bytes = 2 * NST * STAGE_B + (2 * BN + 2 * BM) * 4;  // 84032
  static bool attr_set = false;
  if (!attr_set) {
    cudaFuncSetAttribute(energy_fp16_kernel,
                         cudaFuncAttributeMaxDynamicSharedMemorySize, smem_bytes);
    attr_set = true;
  }

  compact_kernel<<<BDIM, 256>>>(mask);
  enc2h_gather<<<dim3(SDIM, BDIM), 256>>>((const float4*)enc);
  wt_kernel<<<dim3(32, 64), dim3(32, 8)>>>(W);
  hwh_part_kernel<<<dim3(4, BDIM, 8), 256>>>(hidden, W, b_attn);
  hwh_reduce_kernel<<<BDIM * NDIM / 256, 256>>>();
  energy_fp16_kernel<<<dim3(8, BDIM * 16), 256, smem_bytes>>>(v);
  softmax_kernel<<<BDIM, 256>>>(mask, out);
}

// round 14
// speedup vs baseline: 2.1540x; 1.0105x over previous
#include <cuda_runtime.h>
#include <cuda_fp16.h>
#include <cstdint>
#include <math.h>

#define BDIM 64
#define SDIM 2048
#define HDIM 1024
#define KDIM 2048   // 2H (contraction)
#define NDIM 1024   // H  (energy dim)

#define BM 128
#define BN 128
#define BK 32        // halves per k-tile
#define PADH 40      // row pitch in halves (80B: 16B multiple, conflict-free LDSM)
#define NST 4        // cp.async pipeline stages
#define STAGE_B (BM * PADH * 2)   // bytes per (A or B) stage = 10240

// ---- device scratch (allocation-free rule: __device__ globals) ----
__device__ float  g_hWh[BDIM * NDIM];               // hidden@Wh + b_attn
__device__ float  g_hWhP[8][BDIM * NDIM];           // split-K partials
__device__ float  g_part[8 * BDIM * SDIM];          // per-nTile partial scores
__device__ __half g_encH[(size_t)BDIM * SDIM * KDIM];  // compacted enc fp16
__device__ __half g_WhT[(size_t)NDIM * KDIM];          // We^T fp16 [N][K]
__device__ int    g_idx[BDIM * SDIM];               // compacted s' -> s
__device__ int    g_cnt[BDIM];                      // surviving rows per batch

// ---------------------------------------------------------------- helpers
__device__ __forceinline__ void cpa16(void* s, const void* g) {
  uint32_t sa = (uint32_t)__cvta_generic_to_shared(s);
  asm volatile("cp.async.cg.shared.global [%0], [%1], 16;\n" :: "r"(sa), "l"(g));
}
__device__ __forceinline__ uint32_t smem_u32(const void* p) {
  uint32_t a;
  asm("{ .reg .u64 t; cvta.to.shared.u64 t, %1; cvt.u32.u64 %0, t; }" : "=r"(a) : "l"(p));
  return a;
}
__device__ __forceinline__ void mma16(float* d, const uint32_t* a, const uint32_t* b) {
  asm volatile(
    "mma.sync.aligned.m16n8k16.row.col.f32.f16.f16.f32 "
    "{%0,%1,%2,%3}, {%4,%5,%6,%7}, {%8,%9}, {%0,%1,%2,%3};\n"
    : "+f"(d[0]), "+f"(d[1]), "+f"(d[2]), "+f"(d[3])
    : "r"(a[0]), "r"(a[1]), "r"(a[2]), "r"(a[3]), "r"(b[0]), "r"(b[1]));
}
__device__ __forceinline__ void ldsm4(uint32_t& r0, uint32_t& r1,
                                      uint32_t& r2, uint32_t& r3, uint32_t addr) {
  asm volatile("ldmatrix.sync.aligned.m8n8.x4.shared.b16 {%0,%1,%2,%3}, [%4];"
               : "=r"(r0), "=r"(r1), "=r"(r2), "=r"(r3) : "r"(addr));
}

// --------------------------- kernel A: per-batch mask compaction (scan)
__global__ void compact_kernel(const int* __restrict__ mask) {
  const int b = blockIdx.x;        // 64
  const int tid = threadIdx.x;     // 256, each handles 8 consecutive s
  __shared__ int wsum[8];
  int m[8];
  int c = 0;
  const int base = b * SDIM + tid * 8;
  #pragma unroll
  for (int i = 0; i < 8; i++) { m[i] = mask[base + i]; c += (m[i] != 0); }
  int inc = c;
  #pragma unroll
  for (int o = 1; o < 32; o <<= 1) {
    int y = __shfl_up_sync(0xffffffffu, inc, o);
    if ((tid & 31) >= o) inc += y;
  }
  if ((tid & 31) == 31) wsum[tid >> 5] = inc;
  __syncthreads();
  if (tid < 8) {
    int v = wsum[tid];
    #pragma unroll
    for (int o = 1; o < 8; o <<= 1) {
      int y = __shfl_up_sync(0x000000ffu, v, o);
      if (tid >= o) v += y;
    }
    wsum[tid] = v;
  }
  __syncthreads();
  int pos = (inc - c) + ((tid >= 32) ? wsum[(tid >> 5) - 1] : 0);
  #pragma unroll
  for (int i = 0; i < 8; i++)
    if (m[i] != 0) g_idx[b * SDIM + (pos++)] = tid * 8 + i;
  if (tid == 255) g_cnt[b] = wsum[7];
}

// ------------- kernel B: gather surviving enc rows -> compacted fp16
__global__ void enc2h_gather(const float4* __restrict__ enc4) {
  const int b  = blockIdx.y;
  const int sp = blockIdx.x;                 // compacted row
  if (sp >= g_cnt[b]) return;
  const int s = g_idx[b * SDIM + sp];
  const float4* src = enc4 + ((size_t)b * SDIM + s) * (KDIM / 4);
  __half2* dst = (__half2*)(g_encH + ((size_t)b * SDIM + sp) * KDIM);
  for (int i = threadIdx.x; i < KDIM / 4; i += 256) {
    float4 x = src[i];
    dst[i * 2]     = __floats2half2_rn(x.x, x.y);
    dst[i * 2 + 1] = __floats2half2_rn(x.z, x.w);
  }
}

// ----------------------- kernel 0: WhT[n][k] = fp16(W[H+k][n]) transpose
__global__ void wt_kernel(const float* __restrict__ W) {
  __shared__ float t[32][33];
  const int n0 = blockIdx.x * 32;
  const int k0 = blockIdx.y * 32;
  const int tx = threadIdx.x, ty = threadIdx.y;   // 32 x 8
  #pragma unroll
  for (int i = 0; i < 4; i++)
    t[ty + i * 8][tx] = W[(size_t)(HDIM + k0 + ty + i * 8) * NDIM + n0 + tx];
  __syncthreads();
  #pragma unroll
  for (int i = 0; i < 4; i++)
    g_WhT[(size_t)(n0 + ty + i * 8) * KDIM + k0 + tx] =
        __float2half_rn(t[tx][ty + i * 8]);
}

// ------------------------------- kernel 1a: hWh split-K partials (MLP x8)
__global__ void hwh_part_kernel(const float* __restrict__ hidden,
                                const float* __restrict__ W,
                                const float* __restrict__ b_attn) {
  const int n  = blockIdx.x * 256 + threadIdx.x;   // 4 blocks
  const int b  = blockIdx.y;                       // 64
  const int kz = blockIdx.z;                       // 8 k-splits of 128
  const float* hrow = hidden + (long long)b * HDIM + kz * 128;
  const float* Wp   = W + (size_t)(kz * 128) * NDIM + n;
  float a0 = 0.f, a1 = 0.f, a2 = 0.f, a3 = 0.f;
  #pragma unroll 8
  for (int h = 0; h < 128; h += 4) {
    a0 = fmaf(hrow[h    ], Wp[(size_t)(h    ) * NDIM], a0);
    a1 = fmaf(hrow[h + 1], Wp[(size_t)(h + 1) * NDIM], a1);
    a2 = fmaf(hrow[h + 2], Wp[(size_t)(h + 2) * NDIM], a2);
    a3 = fmaf(hrow[h + 3], Wp[(size_t)(h + 3) * NDIM], a3);
  }
  g_hWhP[kz][b * NDIM + n] =
      (a0 + a1) + (a2 + a3) + ((kz == 0) ? b_attn[n] : 0.f);
}

// ------------------------------- kernel 1b: reduce split-K partials
__global__ void hwh_reduce_kernel() {
  const int i = blockIdx.x * 256 + threadIdx.x;    // 256 blocks
  float s = 0.f;
  #pragma unroll
  for (int j = 0; j < 8; j++) s += g_hWhP[j][i];
  g_hWh[i] = s;
}

// ------------------------------------------------ tile loader (cp.async)
__device__ __forceinline__ void load_tile(__half (*As)[PADH], __half (*Bs)[PADH],
                                          const __half* Ag, const __half* Bg,
                                          int kh, int tid) {
  #pragma unroll
  for (int i = 0; i < 2; i++) {
    int c = tid * 2 + i;
    int r = c >> 2, q = c & 3;
    cpa16(&As[r][q * 8], Ag + (size_t)r * KDIM + kh + q * 8);
    cpa16(&Bs[r][q * 8], Bg + (size_t)r * KDIM + kh + q * 8);
  }
  asm volatile("cp.async.commit_group;\n" ::: "memory");
}

// ------------- kernel 2: fused E = enc@We (fp16 MMA) ; p = v·tanh(E+hWh)
// grid: (8 n-tiles, 64 batches x 16 m-tiles) — per-batch compacted rows
__global__ __launch_bounds__(256, 2)
void energy_fp16_kernel(const float* __restrict__ v) {
  const int b    = blockIdx.y >> 4;       // batch
  const int tile = blockIdx.y & 15;       // m-tile within batch (compacted)
  const int cnt  = g_cnt[b];
  if (tile * BM >= cnt) return;           // dead tile: exit before barriers

  extern __shared__ __align__(16) char dynsm[];
  __half (*As)[BM][PADH] = reinterpret_cast<__half(*)[BM][PADH]>(dynsm);
  __half (*Bs)[BM][PADH] = reinterpret_cast<__half(*)[BM][PADH]>(dynsm + NST * STAGE_B);
  float* s_hwh = (float*)(dynsm + 2 * NST * STAGE_B);
  float* s_v   = s_hwh + BN;
  float* s_red = s_v + BN;                 // [2][BM]

  const int tid  = threadIdx.x;
  const int lane = tid & 31;
  const int wid  = tid >> 5;
  const int wm   = wid & 3;    // warp grid 4(M) x 2(N)
  const int wn   = wid >> 2;
  const int grp  = lane >> 2;  // 0..7
  const int qp   = lane & 3;   // 0..3

  const int n0 = blockIdx.x * BN;          // x fastest => L2 reuse of A
  const int row0c = tile * BM;             // compacted row base within batch

  const __half* Ag = g_encH + ((size_t)b * SDIM + row0c) * KDIM;
  const __half* Bg = g_WhT + (size_t)n0 * KDIM;

  // ---- ldmatrix per-lane byte offsets (within one stage) ----
  const int l8 = lane & 7;
  const int lm = lane >> 3;
  uint32_t aOff[2];
  #pragma unroll
  for (int mf = 0; mf < 2; mf++) {
    const int row = wm * 32 + mf * 16 + l8 + (lm & 1) * 8;
    const int col = (lm >> 1) * 8;
    aOff[mf] = (uint32_t)((row * PADH + col) * 2);
  }
  uint32_t bOff[4];
  #pragma unroll
  for (int nfp = 0; nfp < 4; nfp++) {
    const int row = wn * 64 + nfp * 16 + l8 + (lm >> 1) * 8;
    const int col = (lm & 1) * 8;
    bOff[nfp] = (uint32_t)((row * PADH + col) * 2);
  }
  const uint32_t aB0 = smem_u32(&As[0][0][0]);
  const uint32_t bB0 = smem_u32(&Bs[0][0][0]);

  float acc[2][8][4];
  #pragma unroll
  for (int i = 0; i < 2; i++)
    #pragma unroll
    for (int j = 0; j < 8; j++)
      #pragma unroll
      for (int e = 0; e < 4; e++) acc[i][j][e] = 0.f;

  const int KT = KDIM / BK;  // 64
  load_tile(As[0], Bs[0], Ag, Bg, 0 * BK, tid);
  load_tile(As[1], Bs[1], Ag, Bg, 1 * BK, tid);
  load_tile(As[2], Bs[2], Ag, Bg, 2 * BK, tid);
  if (tid < BN) {
    s_hwh[tid] = g_hWh[(size_t)b * NDIM + n0 + tid];
    s_v[tid]   = v[n0 + tid];
  }

  for (int kt = 0; kt < KT; kt++) {
    const int cur = kt & 3;
    if (kt < KT - 2)
      asm volatile("cp.async.wait_group 2;\n" ::: "memory");
    else if (kt == KT - 2)
      asm volatile("cp.async.wait_group 1;\n" ::: "memory");
    else
      asm volatile("cp.async.wait_group 0;\n" ::: "memory");
    __syncthreads();   // stage `cur` visible; stage (kt+3)%4 free (read in kt-1)

    const int ktn = kt + 3;                 // refill overlaps compute below
    if (ktn < KT) {
      const int sn = ktn & 3;
      load_tile(As[sn], Bs[sn], Ag, Bg, ktn * BK, tid);
    }

    const uint32_t aBase = aB0 + (uint32_t)cur * STAGE_B;
    const uint32_t bBase = bB0 + (uint32_t)cur * STAGE_B;
    #pragma unroll
    for (int ks = 0; ks < 2; ks++) {
      const uint32_t kByte = (uint32_t)(ks * 16 * 2);
      uint32_t a[2][4];
      #pragma unroll
      for (int mf = 0; mf < 2; mf++)
        ldsm4(a[mf][0], a[mf][1], a[mf][2], a[mf][3], aBase + aOff[mf] + kByte);
      uint32_t bb[8][2];
      #pragma unroll
      for (int nfp = 0; nfp < 4; nfp++)
        ldsm4(bb[nfp * 2][0], bb[nfp * 2][1], bb[nfp * 2 + 1][0], bb[nfp * 2 + 1][1],
              bBase + bOff[nfp] + kByte);
      #pragma unroll
      for (int mf = 0; mf < 2; mf++)
        #pragma unroll
        for (int nf = 0; nf < 8; nf++)
          mma16(acc[mf][nf], a[mf], bb[nf]);
    }
  }
  __syncthreads();

  // ---------------- epilogue: + hWh, tanh, dot v, reduce over this n-tile
  float p[2][2] = {{0.f, 0.f}, {0.f, 0.f}};
  #pragma unroll
  for (int mf = 0; mf < 2; mf++)
    #pragma unroll
    for (int nf = 0; nf < 8; nf++)
      #pragma unroll
      for (int e = 0; e < 4; e++) {
        const int nl = wn * 64 + nf * 8 + qp * 2 + (e & 1);
        const float en = tanhf(acc[mf][nf][e] + s_hwh[nl]);
        p[mf][e >> 1] += en * s_v[nl];
      }
  #pragma unroll
  for (int mf = 0; mf < 2; mf++)
    #pragma unroll
    for (int h = 0; h < 2; h++) {
      float x = p[mf][h];
      x += __shfl_xor_sync(0xffffffffu, x, 1);
      x += __shfl_xor_sync(0xffffffffu, x, 2);
      if (qp == 0) s_red[wn * BM + wm * 32 + mf * 16 + h * 8 + grp] = x;
    }
  __syncthreads();
  if (tid < BM) {
    const int sp = row0c + tid;
    if (sp < cnt) {                        // skip padding rows
      const int s = g_idx[b * SDIM + sp];  // scatter to original position
      g_part[(size_t)blockIdx.x * (BDIM * SDIM) + (size_t)b * SDIM + s] =
          s_red[tid] + s_red[BM + tid];
    }
  }
}

// ------------------------------------------ kernel 3: mask + softmax(S)
__global__ void softmax_kernel(const int* __restrict__ mask,
                               float* __restrict__ out) {
  const int bq = blockIdx.x;
  const int tid = threadIdx.x;
  float loc[8];
  float mx = -1e30f;
  #pragma unroll
  for (int i = 0; i < 8; i++) {
    const long long idx = (long long)bq * SDIM + i * 256 + tid;
    float sc = 0.0f;
    #pragma unroll
    for (int j = 0; j < 8; j++) sc += g_part[(long long)j * (BDIM * SDIM) + idx];
    if (mask[idx] == 0) sc = -1e9f;
    loc[i] = sc;
    mx = fmaxf(mx, sc);
  }
  __shared__ float sm[8];
  #pragma unroll
  for (int o = 16; o > 0; o >>= 1) mx = fmaxf(mx, __shfl_xor_sync(~0u, mx, o));
  if ((tid & 31) == 0) sm[tid >> 5] = mx;
  __syncthreads();
  if (tid < 32) {
    float t = (tid < 8) ? sm[tid] : -1e30f;
    #pragma unroll
    for (int o = 4; o > 0; o >>= 1) t = fmaxf(t, __shfl_xor_sync(~0u, t, o));
    if (tid == 0) sm[0] = t;
  }
  __syncthreads();
  mx = sm[0];

  float sum = 0.0f;
  #pragma unroll
  for (int i = 0; i < 8; i++) { loc[i] = expf(loc[i] - mx); sum += loc[i]; }
  __shared__ float ss[8];
  #pragma unroll
  for (int o = 16; o > 0; o >>= 1) sum += __shfl_xor_sync(~0u, sum, o);
  if ((tid & 31) == 0) ss[tid >> 5] = sum;
  __syncthreads();
  if (tid < 32) {
    float t = (tid < 8) ? ss[tid] : 0.0f;
    #pragma unroll
    for (int o = 4; o > 0; o >>= 1) t += __shfl_xor_sync(~0u, t, o);
    if (tid == 0) ss[0] = t;
  }
  __syncthreads();
  const float inv = 1.0f / ss[0];
  #pragma unroll
  for (int i = 0; i < 8; i++)
    out[(long long)bq * SDIM + i * 256 + tid] = loc[i] * inv;
}

// ----------------------------------------------------------------- launch
extern "C" void kernel_launch(void* const* d_in, const int* in_sizes, int n_in,
                              void* d_out, int out_size) {
  const float* hidden = nullptr;
  const float* enc    = nullptr;
  const int*   mask   = nullptr;
  const float* W      = nullptr;
  const float* b_attn = nullptr;
  const float* v      = nullptr;

  for (int pass = 0; pass < 2; pass++) {      // elements, then bytes
    const long long mul = (pass == 0) ? 1LL : 4LL;
    hidden = enc = W = b_attn = v = nullptr; mask = nullptr;
    for (int i = 0; i < n_in; i++) {
      const long long sz = (long long)in_sizes[i];
      if      (sz == 65536LL * mul)     hidden = (const float*)d_in[i];
      else if (sz == 268435456LL * mul) enc    = (const float*)d_in[i];
      else if (sz == 131072LL * mul)    mask   = (const int*)  d_in[i];
      else if (sz == 3145728LL * mul)   W      = (const float*)d_in[i];
      else if (sz == 1024LL * mul) {
        if (!b_attn) b_attn = (const float*)d_in[i];
        else         v      = (const float*)d_in[i];
      }
    }
    if (hidden && enc && mask && W && b_attn && v) break;
  }
  if (!hidden || !enc || !mask || !W || !b_attn || !v) {
    hidden = (const float*)d_in[0];
    enc    = (const float*)d_in[1];
    mask   = (const int*)  d_in[2];
    W      = (const float*)d_in[3];
    b_attn = (const float*)d_in[4];
    v      = (const float*)d_in[5];
  }
  float* out = (float*)d_out;   // (B,S) float32

  const int smem_bytes = 2 * NST * STAGE_B + (2 * BN + 2 * BM) * 4;  // 84032
  static bool init_done = false;
  static cudaStream_t s1, s2;
  static cudaEvent_t eFork, eJoin1, eJoin2;
  if (!init_done) {
    cudaFuncSetAttribute(energy_fp16_kernel,
                         cudaFuncAttributeMaxDynamicSharedMemorySize, smem_bytes);
    cudaStreamCreateWithFlags(&s1, cudaStreamNonBlocking);
    cudaStreamCreateWithFlags(&s2, cudaStreamNonBlocking);
    cudaEventCreateWithFlags(&eFork,  cudaEventDisableTiming);
    cudaEventCreateWithFlags(&eJoin1, cudaEventDisableTiming);
    cudaEventCreateWithFlags(&eJoin2, cudaEventDisableTiming);
    init_done = true;
  }

  // fork: side streams branch off the captured (default) stream
  cudaEventRecord(eFork, 0);
  cudaStreamWaitEvent(s1, eFork, 0);
  cudaStreamWaitEvent(s2, eFork, 0);

  // s1: We transpose (independent of mask path)
  wt_kernel<<<dim3(32, 64), dim3(32, 8), 0, s1>>>(W);
  // s2: hWh split-K + reduce (independent of mask path)
  hwh_part_kernel<<<dim3(4, BDIM, 8), 256, 0, s2>>>(hidden, W, b_attn);
  hwh_reduce_kernel<<<BDIM * NDIM / 256, 256, 0, s2>>>();
  // main stream: compact -> gather (the long pole of the prep phase)
  compact_kernel<<<BDIM, 256>>>(mask);
  enc2h_gather<<<dim3(SDIM, BDIM), 256>>>((const float4*)enc);

  // join: energy needs g_encH (main), g_WhT (s1), g_hWh (s2)
  cudaEventRecord(eJoin1, s1);
  cudaEventRecord(eJoin2, s2);
  cudaStreamWaitEvent(0, eJoin1, 0);
  cudaStreamWaitEvent(0, eJoin2, 0);

  energy_fp16_kernel<<<dim3(8, BDIM * 16), 256, smem_bytes>>>(v);
  softmax_kernel<<<BDIM, 256>>>(mask, out);
}

// round 15
// speedup vs baseline: 2.2693x; 1.0536x over previous
#include <cuda_runtime.h>
#include <cuda_fp16.h>
#include <cstdint>
#include <math.h>

#define BDIM 64
#define SDIM 2048
#define HDIM 1024
#define KDIM 2048   // 2H (contraction)
#define NDIM 1024   // H  (energy dim)

#define BM 128
#define BN 128
#define BK 32        // halves per k-tile
#define PADH 40      // row pitch in halves (80B: 16B multiple, conflict-free LDSM)
#define NST 4        // cp.async pipeline stages
#define STAGE_B (BM * PADH * 2)   // bytes per (A or B) stage = 10240

// ---- device scratch (allocation-free rule: __device__ globals) ----
__device__ float  g_hWh[BDIM * NDIM];               // hidden@Wh + b_attn
__device__ float  g_hWhP[8][BDIM * NDIM];           // split-K partials
__device__ float  g_part[8 * BDIM * SDIM];          // per-nTile partial scores
__device__ __half g_encH[(size_t)BDIM * SDIM * KDIM];  // globally packed enc fp16
__device__ __half g_WhT[(size_t)NDIM * KDIM];          // We^T fp16 [N][K]
__device__ int    g_idx[BDIM * SDIM];               // per-batch compacted sp -> s
__device__ int    g_gidx[BDIM * SDIM];              // global packed row -> b*S+s
__device__ int    g_cnt[BDIM];                      // surviving rows per batch
__device__ int    g_off[BDIM];                      // exclusive scan of g_cnt
__device__ int    g_total;                          // total surviving rows

// ---------------------------------------------------------------- helpers
__device__ __forceinline__ void cpa16(void* s, const void* g) {
  uint32_t sa = (uint32_t)__cvta_generic_to_shared(s);
  asm volatile("cp.async.cg.shared.global [%0], [%1], 16;\n" :: "r"(sa), "l"(g));
}
__device__ __forceinline__ uint32_t smem_u32(const void* p) {
  uint32_t a;
  asm("{ .reg .u64 t; cvta.to.shared.u64 t, %1; cvt.u32.u64 %0, t; }" : "=r"(a) : "l"(p));
  return a;
}
__device__ __forceinline__ void mma16(float* d, const uint32_t* a, const uint32_t* b) {
  asm volatile(
    "mma.sync.aligned.m16n8k16.row.col.f32.f16.f16.f32 "
    "{%0,%1,%2,%3}, {%4,%5,%6,%7}, {%8,%9}, {%0,%1,%2,%3};\n"
    : "+f"(d[0]), "+f"(d[1]), "+f"(d[2]), "+f"(d[3])
    : "r"(a[0]), "r"(a[1]), "r"(a[2]), "r"(a[3]), "r"(b[0]), "r"(b[1]));
}
__device__ __forceinline__ void ldsm4(uint32_t& r0, uint32_t& r1,
                                      uint32_t& r2, uint32_t& r3, uint32_t addr) {
  asm volatile("ldmatrix.sync.aligned.m8n8.x4.shared.b16 {%0,%1,%2,%3}, [%4];"
               : "=r"(r0), "=r"(r1), "=r"(r2), "=r"(r3) : "r"(addr));
}

// --------------------------- kernel A: per-batch mask compaction (scan)
__global__ void compact_kernel(const int* __restrict__ mask) {
  const int b = blockIdx.x;        // 64
  const int tid = threadIdx.x;     // 256, each handles 8 consecutive s
  __shared__ int wsum[8];
  int m[8];
  int c = 0;
  const int base = b * SDIM + tid * 8;
  #pragma unroll
  for (int i = 0; i < 8; i++) { m[i] = mask[base + i]; c += (m[i] != 0); }
  int inc = c;
  #pragma unroll
  for (int o = 1; o < 32; o <<= 1) {
    int y = __shfl_up_sync(0xffffffffu, inc, o);
    if ((tid & 31) >= o) inc += y;
  }
  if ((tid & 31) == 31) wsum[tid >> 5] = inc;
  __syncthreads();
  if (tid < 8) {
    int v = wsum[tid];
    #pragma unroll
    for (int o = 1; o < 8; o <<= 1) {
      int y = __shfl_up_sync(0x000000ffu, v, o);
      if (tid >= o) v += y;
    }
    wsum[tid] = v;
  }
  __syncthreads();
  int pos = (inc - c) + ((tid >= 32) ? wsum[(tid >> 5) - 1] : 0);
  #pragma unroll
  for (int i = 0; i < 8; i++)
    if (m[i] != 0) g_idx[b * SDIM + (pos++)] = tid * 8 + i;
  if (tid == 255) g_cnt[b] = wsum[7];
}

// --------------------------- kernel A2: exclusive scan of g_cnt (64 vals)
__global__ void offs_kernel() {
  const int tid = threadIdx.x;     // 64
  const int c = g_cnt[tid];
  int inc = c;
  #pragma unroll
  for (int o = 1; o < 32; o <<= 1) {
    int y = __shfl_up_sync(0xffffffffu, inc, o);
    if ((tid & 31) >= o) inc += y;
  }
  __shared__ int w0;
  if (tid == 31) w0 = inc;
  __syncthreads();
  const int ex = (inc - c) + ((tid >= 32) ? w0 : 0);
  g_off[tid] = ex;
  if (tid == 63) g_total = ex + c;
}

// ------------- kernel B: gather surviving rows -> globally packed fp16
__global__ void enc2h_gather(const float4* __restrict__ enc4) {
  const int b  = blockIdx.y;
  const int sp = blockIdx.x;                 // per-batch compacted row
  if (sp >= g_cnt[b]) return;
  const int s  = g_idx[b * SDIM + sp];
  const int gr = g_off[b] + sp;              // global packed row
  const float4* src = enc4 + ((size_t)b * SDIM + s) * (KDIM / 4);
  __half2* dst = (__half2*)(g_encH + (size_t)gr * KDIM);
  for (int i = threadIdx.x; i < KDIM / 4; i += 256) {
    float4 x = src[i];
    dst[i * 2]     = __floats2half2_rn(x.x, x.y);
    dst[i * 2 + 1] = __floats2half2_rn(x.z, x.w);
  }
  if (threadIdx.x == 0) g_gidx[gr] = b * SDIM + s;
}

// ----------------------- kernel 0: WhT[n][k] = fp16(W[H+k][n]) transpose
__global__ void wt_kernel(const float* __restrict__ W) {
  __shared__ float t[32][33];
  const int n0 = blockIdx.x * 32;
  const int k0 = blockIdx.y * 32;
  const int tx = threadIdx.x, ty = threadIdx.y;   // 32 x 8
  #pragma unroll
  for (int i = 0; i < 4; i++)
    t[ty + i * 8][tx] = W[(size_t)(HDIM + k0 + ty + i * 8) * NDIM + n0 + tx];
  __syncthreads();
  #pragma unroll
  for (int i = 0; i < 4; i++)
    g_WhT[(size_t)(n0 + ty + i * 8) * KDIM + k0 + tx] =
        __float2half_rn(t[tx][ty + i * 8]);
}

// ------------------------------- kernel 1a: hWh split-K partials (MLP x8)
__global__ void hwh_part_kernel(const float* __restrict__ hidden,
                                const float* __restrict__ W,
                                const float* __restrict__ b_attn) {
  const int n  = blockIdx.x * 256 + threadIdx.x;   // 4 blocks
  const int b  = blockIdx.y;                       // 64
  const int kz = blockIdx.z;                       // 8 k-splits of 128
  const float* hrow = hidden + (long long)b * HDIM + kz * 128;
  const float* Wp   = W + (size_t)(kz * 128) * NDIM + n;
  float a0 = 0.f, a1 = 0.f, a2 = 0.f, a3 = 0.f;
  #pragma unroll 8
  for (int h = 0; h < 128; h += 4) {
    a0 = fmaf(hrow[h    ], Wp[(size_t)(h    ) * NDIM], a0);
    a1 = fmaf(hrow[h + 1], Wp[(size_t)(h + 1) * NDIM], a1);
    a2 = fmaf(hrow[h + 2], Wp[(size_t)(h + 2) * NDIM], a2);
    a3 = fmaf(hrow[h + 3], Wp[(size_t)(h + 3) * NDIM], a3);
  }
  g_hWhP[kz][b * NDIM + n] =
      (a0 + a1) + (a2 + a3) + ((kz == 0) ? b_attn[n] : 0.f);
}

// ------------------------------- kernel 1b: reduce split-K partials
__global__ void hwh_reduce_kernel() {
  const int i = blockIdx.x * 256 + threadIdx.x;    // 256 blocks
  float s = 0.f;
  #pragma unroll
  for (int j = 0; j < 8; j++) s += g_hWhP[j][i];
  g_hWh[i] = s;
}

// ------------------------------------------------ tile loader (cp.async)
__device__ __forceinline__ void load_tile(__half (*As)[PADH], __half (*Bs)[PADH],
                                          const __half* Ag, const __half* Bg,
                                          int kh, int tid) {
  #pragma unroll
  for (int i = 0; i < 2; i++) {
    int c = tid * 2 + i;
    int r = c >> 2, q = c & 3;
    cpa16(&As[r][q * 8], Ag + (size_t)r * KDIM + kh + q * 8);
    cpa16(&Bs[r][q * 8], Bg + (size_t)r * KDIM + kh + q * 8);
  }
  asm volatile("cp.async.commit_group;\n" ::: "memory");
}

// ------------- kernel 2: fused E = enc@We (fp16 MMA) ; p = v·tanh(E+hWh)
// grid: (8 n-tiles, 1024 global packed m-tiles); dead tiles exit early
__global__ __launch_bounds__(256, 2)
void energy_fp16_kernel(const float* __restrict__ v) {
  const int t = blockIdx.y;               // global packed m-tile
  const int total = g_total;
  if (t * BM >= total) return;            // dead tile: exit before barriers

  extern __shared__ __align__(16) char dynsm[];
  __half (*As)[BM][PADH] = reinterpret_cast<__half(*)[BM][PADH]>(dynsm);
  __half (*Bs)[BM][PADH] = reinterpret_cast<__half(*)[BM][PADH]>(dynsm + NST * STAGE_B);
  float* s_v   = (float*)(dynsm + 2 * NST * STAGE_B);
  float* s_red = s_v + BN;                 // [2][BM]

  const int tid  = threadIdx.x;
  const int lane = tid & 31;
  const int wid  = tid >> 5;
  const int wm   = wid & 3;    // warp grid 4(M) x 2(N)
  const int wn   = wid >> 2;
  const int grp  = lane >> 2;  // 0..7
  const int qp   = lane & 3;   // 0..3

  const int n0 = blockIdx.x * BN;          // x fastest => L2 reuse of A
  const int row0 = t * BM;                 // global packed row base

  const __half* Ag = g_encH + (size_t)row0 * KDIM;
  const __half* Bg = g_WhT + (size_t)n0 * KDIM;

  // ---- ldmatrix per-lane byte offsets (within one stage) ----
  const int l8 = lane & 7;
  const int lm = lane >> 3;
  uint32_t aOff[2];
  #pragma unroll
  for (int mf = 0; mf < 2; mf++) {
    const int row = wm * 32 + mf * 16 + l8 + (lm & 1) * 8;
    const int col = (lm >> 1) * 8;
    aOff[mf] = (uint32_t)((row * PADH + col) * 2);
  }
  uint32_t bOff[4];
  #pragma unroll
  for (int nfp = 0; nfp < 4; nfp++) {
    const int row = wn * 64 + nfp * 16 + l8 + (lm >> 1) * 8;
    const int col = (lm & 1) * 8;
    bOff[nfp] = (uint32_t)((row * PADH + col) * 2);
  }
  const uint32_t aB0 = smem_u32(&As[0][0][0]);
  const uint32_t bB0 = smem_u32(&Bs[0][0][0]);

  float acc[2][8][4];
  #pragma unroll
  for (int i = 0; i < 2; i++)
    #pragma unroll
    for (int j = 0; j < 8; j++)
      #pragma unroll
      for (int e = 0; e < 4; e++) acc[i][j][e] = 0.f;

  const int KT = KDIM / BK;  // 64
  load_tile(As[0], Bs[0], Ag, Bg, 0 * BK, tid);
  load_tile(As[1], Bs[1], Ag, Bg, 1 * BK, tid);
  load_tile(As[2], Bs[2], Ag, Bg, 2 * BK, tid);
  if (tid < BN) s_v[tid] = v[n0 + tid];

  for (int kt = 0; kt < KT; kt++) {
    const int cur = kt & 3;
    if (kt < KT - 2)
      asm volatile("cp.async.wait_group 2;\n" ::: "memory");
    else if (kt == KT - 2)
      asm volatile("cp.async.wait_group 1;\n" ::: "memory");
    else
      asm volatile("cp.async.wait_group 0;\n" ::: "memory");
    __syncthreads();   // stage `cur` visible; stage (kt+3)%4 free (read in kt-1)

    const int ktn = kt + 3;                 // refill overlaps compute below
    if (ktn < KT) {
      const int sn = ktn & 3;
      load_tile(As[sn], Bs[sn], Ag, Bg, ktn * BK, tid);
    }

    const uint32_t aBase = aB0 + (uint32_t)cur * STAGE_B;
    const uint32_t bBase = bB0 + (uint32_t)cur * STAGE_B;
    #pragma unroll
    for (int ks = 0; ks < 2; ks++) {
      const uint32_t kByte = (uint32_t)(ks * 16 * 2);
      uint32_t a[2][4];
      #pragma unroll
      for (int mf = 0; mf < 2; mf++)
        ldsm4(a[mf][0], a[mf][1], a[mf][2], a[mf][3], aBase + aOff[mf] + kByte);
      uint32_t bb[8][2];
      #pragma unroll
      for (int nfp = 0; nfp < 4; nfp++)
        ldsm4(bb[nfp * 2][0], bb[nfp * 2][1], bb[nfp * 2 + 1][0], bb[nfp * 2 + 1][1],
              bBase + bOff[nfp] + kByte);
      #pragma unroll
      for (int mf = 0; mf < 2; mf++)
        #pragma unroll
        for (int nf = 0; nf < 8; nf++)
          mma16(acc[mf][nf], a[mf], bb[nf]);
    }
  }
  __syncthreads();

  // ------- epilogue: + hWh (per-row batch, L2), tanh, dot v, n-tile reduce
  float p[2][2] = {{0.f, 0.f}, {0.f, 0.f}};
  #pragma unroll
  for (int mf = 0; mf < 2; mf++)
    #pragma unroll
    for (int half = 0; half < 2; half++) {
      const int gr = row0 + wm * 32 + mf * 16 + grp + half * 8;
      const bool valid = gr < total;
      const int gidx = valid ? g_gidx[gr] : 0;
      const float* hw = g_hWh + (size_t)(gidx >> 11) * NDIM + n0;  // S=2048
      float ps = 0.f;
      #pragma unroll
      for (int nf = 0; nf < 8; nf++)
        #pragma unroll
        for (int eo = 0; eo < 2; eo++) {
          // C frag: e = 2*half+eo -> row (grp + 8*half), col qp*2+eo
          const int nl = wn * 64 + nf * 8 + qp * 2 + eo;
          ps += tanhf(acc[mf][nf][half * 2 + eo] + hw[nl]) * s_v[nl];
        }
      p[mf][half] = ps;
    }
  #pragma unroll
  for (int mf = 0; mf < 2; mf++)
    #pragma unroll
    for (int h = 0; h < 2; h++) {
      float x = p[mf][h];
      x += __shfl_xor_sync(0xffffffffu, x, 1);
      x += __shfl_xor_sync(0xffffffffu, x, 2);
      if (qp == 0) s_red[wn * BM + wm * 32 + mf * 16 + h * 8 + grp] = x;
    }
  __syncthreads();
  if (tid < BM) {
    const int gr = row0 + tid;
    if (gr < total) {
      const int gidx = g_gidx[gr];          // scatter to original (b,s)
      g_part[(size_t)blockIdx.x * (BDIM * SDIM) + gidx] =
          s_red[tid] + s_red[BM + tid];
    }
  }
}

// ------------------------------------------ kernel 3: mask + softmax(S)
__global__ void softmax_kernel(const int* __restrict__ mask,
                               float* __restrict__ out) {
  const int bq = blockIdx.x;
  const int tid = threadIdx.x;
  float loc[8];
  float mx = -1e30f;
  #pragma unroll
  for (int i = 0; i < 8; i++) {
    const long long idx = (long long)bq * SDIM + i * 256 + tid;
    float sc = 0.0f;
    #pragma unroll
    for (int j = 0; j < 8; j++) sc += g_part[(long long)j * (BDIM * SDIM) + idx];
    if (mask[idx] == 0) sc = -1e9f;
    loc[i] = sc;
    mx = fmaxf(mx, sc);
  }
  __shared__ float sm[8];
  #pragma unroll
  for (int o = 16; o > 0; o >>= 1) mx = fmaxf(mx, __shfl_xor_sync(~0u, mx, o));
  if ((tid & 31) == 0) sm[tid >> 5] = mx;
  __syncthreads();
  if (tid < 32) {
    float t = (tid < 8) ? sm[tid] : -1e30f;
    #pragma unroll
    for (int o = 4; o > 0; o >>= 1) t = fmaxf(t, __shfl_xor_sync(~0u, t, o));
    if (tid == 0) sm[0] = t;
  }
  __syncthreads();
  mx = sm[0];

  float sum = 0.0f;
  #pragma unroll
  for (int i = 0; i < 8; i++) { loc[i] = expf(loc[i] - mx); sum += loc[i]; }
  __shared__ float ss[8];
  #pragma unroll
  for (int o = 16; o > 0; o >>= 1) sum += __shfl_xor_sync(~0u, sum, o);
  if ((tid & 31) == 0) ss[tid >> 5] = sum;
  __syncthreads();
  if (tid < 32) {
    float t = (tid < 8) ? ss[tid] : 0.0f;
    #pragma unroll
    for (int o = 4; o > 0; o >>= 1) t += __shfl_xor_sync(~0u, t, o);
    if (tid == 0) ss[0] = t;
  }
  __syncthreads();
  const float inv = 1.0f / ss[0];
  #pragma unroll
  for (int i = 0; i < 8; i++)
    out[(long long)bq * SDIM + i * 256 + tid] = loc[i] * inv;
}

// ----------------------------------------------------------------- launch
extern "C" void kernel_launch(void* const* d_in, const int* in_sizes, int n_in,
                              void* d_out, int out_size) {
  const float* hidden = nullptr;
  const float* enc    = nullptr;
  const int*   mask   = nullptr;
  const float* W      = nullptr;
  const float* b_attn = nullptr;
  const float* v      = nullptr;

  for (int pass = 0; pass < 2; pass++) {      // elements, then bytes
    const long long mul = (pass == 0) ? 1LL : 4LL;
    hidden = enc = W = b_attn = v = nullptr; mask = nullptr;
    for (int i = 0; i < n_in; i++) {
      const long long sz = (long long)in_sizes[i];
      if      (sz == 65536LL * mul)     hidden = (const float*)d_in[i];
      else if (sz == 268435456LL * mul) enc    = (const float*)d_in[i];
      else if (sz == 131072LL * mul)    mask   = (const int*)  d_in[i];
      else if (sz == 3145728LL * mul)   W      = (const float*)d_in[i];
      else if (sz == 1024LL * mul) {
        if (!b_attn) b_attn = (const float*)d_in[i];
        else         v      = (const float*)d_in[i];
      }
    }
    if (hidden && enc && mask && W && b_attn && v) break;
  }
  if (!hidden || !enc || !mask || !W || !b_attn || !v) {
    hidden = (const float*)d_in[0];
    enc    = (const float*)d_in[1];
    mask   = (const int*)  d_in[2];
    W      = (const float*)d_in[3];
    b_attn = (const float*)d_in[4];
    v      = (const float*)d_in[5];
  }
  float* out = (float*)d_out;   // (B,S) float32

  const int smem_bytes = 2 * NST * STAGE_B + (BN + 2 * BM) * 4;  // 83520
  static bool init_done = false;
  static cudaStream_t s1, s2;
  static cudaEvent_t eFork, eJoin1, eJoin2;
  if (!init_done) {
    cudaFuncSetAttribute(energy_fp16_kernel,
                         cudaFuncAttributeMaxDynamicSharedMemorySize, smem_bytes);
    cudaStreamCreateWithFlags(&s1, cudaStreamNonBlocking);
    cudaStreamCreateWithFlags(&s2, cudaStreamNonBlocking);
    cudaEventCreateWithFlags(&eFork,  cudaEventDisableTiming);
    cudaEventCreateWithFlags(&eJoin1, cudaEventDisableTiming);
    cudaEventCreateWithFlags(&eJoin2, cudaEventDisableTiming);
    init_done = true;
  }

  // fork: side streams branch off the captured (default) stream
  cudaEventRecord(eFork, 0);
  cudaStreamWaitEvent(s1, eFork, 0);
  cudaStreamWaitEvent(s2, eFork, 0);

  // s1: We transpose (independent of mask path)
  wt_kernel<<<dim3(32, 64), dim3(32, 8), 0, s1>>>(W);
  // s2: hWh split-K + reduce (independent of mask path)
  hwh_part_kernel<<<dim3(4, BDIM, 8), 256, 0, s2>>>(hidden, W, b_attn);
  hwh_reduce_kernel<<<BDIM * NDIM / 256, 256, 0, s2>>>();
  // main stream: compact -> offsets -> gather (long pole of prep)
  compact_kernel<<<BDIM, 256>>>(mask);
  offs_kernel<<<1, 64>>>();
  enc2h_gather<<<dim3(SDIM, BDIM), 256>>>((const float4*)enc);

  // join: energy needs g_encH/g_gidx (main), g_WhT (s1), g_hWh (s2)
  cudaEventRecord(eJoin1, s1);
  cudaEventRecord(eJoin2, s2);
  cudaStreamWaitEvent(0, eJoin1, 0);
  cudaStreamWaitEvent(0, eJoin2, 0);

  energy_fp16_kernel<<<dim3(8, 1024), 256, smem_bytes>>>(v);
  softmax_kernel<<<BDIM, 256>>>(mask, out);
}